// round 6
// baseline (speedup 1.0000x reference)
#include <cuda_runtime.h>
#include <math.h>

#define T_LEN 1024
#define B_SZ  64
#define H_SZ  256
#define D_SZ  256
#define C4    1024          // 4*H, col = j*4 + k (gates of a neuron contiguous)
#define NR    64            // recurrent CTAs (4 neurons / 16 cols each)
#define NW    84            // worker CTAs
#define NTOT  (NR + NW)     // 148 total, all co-resident
#define HS_STRIDE 72        // padded word stride for hs[d][b]

#define Z_MTILES 512        // 65536 rows / 128
#define Z_NTILES 16         // 1024 / 64
#define Y_TILES  2048       // 512 mtiles * 4 ntiles

// ---------------- scratch (static device allocations only) ----------------
__device__ float g_M2[D_SZ * C4];            // folded x-projection  [d][col]
__device__ float g_bias2[C4];
__device__ float g_Wp[H_SZ * C4];            // folded recurrent (Wh - We)
__device__ float g_Z[(size_t)T_LEN * B_SZ * C4];   // t-major: [t][b][1024]
__device__ float g_hT[2][H_SZ * B_SZ];       // h state [j][b], double buffered
__device__ unsigned g_count;                 // grid barrier (recur CTAs)
__device__ unsigned g_epoch;                 // monotonic across replays
__device__ unsigned g_step;                  // steps completed THIS run
__device__ int      g_zdone[Z_MTILES];       // per-mtile completed n-tiles
__device__ unsigned g_ywork;                 // Y tile work queue

// ---------------- acquire/release primitives -------------------------------
__device__ __forceinline__ unsigned ld_acq(const void* p) {
    unsigned v;
    asm volatile("ld.acquire.gpu.b32 %0, [%1];" : "=r"(v) : "l"(p) : "memory");
    return v;
}
__device__ __forceinline__ void st_rel(void* p, unsigned v) {
    asm volatile("st.release.gpu.b32 [%0], %1;" :: "l"(p), "r"(v) : "memory");
}

// ---------------- tf32 mma helpers ----------------------------------------
__device__ __forceinline__ unsigned f2tf32(float x) {
    unsigned r;
    asm("cvt.rna.tf32.f32 %0, %1;" : "=r"(r) : "f"(x));
    return r;
}
__device__ __forceinline__ void mma_tf32(float* c, const unsigned* a,
                                         unsigned b0, unsigned b1) {
    asm volatile(
        "mma.sync.aligned.m16n8k8.row.col.f32.tf32.tf32.f32 "
        "{%0,%1,%2,%3}, {%4,%5,%6,%7}, {%8,%9}, {%0,%1,%2,%3};"
        : "+f"(c[0]), "+f"(c[1]), "+f"(c[2]), "+f"(c[3])
        : "r"(a[0]), "r"(a[1]), "r"(a[2]), "r"(a[3]), "r"(b0), "r"(b1));
}

// ---------------- prep kernels --------------------------------------------
__global__ void k_prepM(const float* __restrict__ Win, const float* __restrict__ Wx,
                        const float* __restrict__ We, const float* __restrict__ b) {
    int k = blockIdx.x, d = blockIdx.y, j = threadIdx.x;
    float acc = Wx[(k * D_SZ + d) * H_SZ + j];
    const float* wrow = &Win[d * H_SZ];
#pragma unroll 8
    for (int e = 0; e < H_SZ; e++)
        acc = fmaf(__ldg(&wrow[e]), __ldg(&We[(k * H_SZ + e) * H_SZ + j]), acc);
    g_M2[d * C4 + j * 4 + k] = acc;
    if (d == 0) g_bias2[j * 4 + k] = b[k * H_SZ + j];
}

__global__ void k_prepW(const float* __restrict__ Wh, const float* __restrict__ We) {
    int k = blockIdx.x, h = blockIdx.y, j = threadIdx.x;
    int src = (k * H_SZ + h) * H_SZ + j;
    g_Wp[h * C4 + j * 4 + k] = Wh[src] - We[src];
}

__global__ void k_reset() {
    int i = threadIdx.x;
    if (i < Z_MTILES) g_zdone[i] = 0;
    if (i == 0) { g_step = 0; g_ywork = 0; g_count = 0; }
    __threadfence();
}

// ---------------- grid barrier for the NR recurrent CTAs -------------------
#define GRIDBAR()                                                          \
    do {                                                                   \
        __syncthreads();                                                   \
        nbar++;                                                            \
        if (tid == 0) {                                                    \
            __threadfence();                                               \
            unsigned prev = atomicAdd(&g_count, 1);                        \
            if (prev == NR - 1) {                                          \
                atomicExch(&g_count, 0);                                   \
                __threadfence();                                           \
                st_rel(&g_step, nbar - 1);                                 \
                st_rel(&g_epoch, base + nbar);                             \
            } else {                                                       \
                while (ld_acq(&g_epoch) - base < nbar) { }                 \
            }                                                              \
            __threadfence();                                               \
        }                                                                  \
        __syncthreads();                                                   \
    } while (0)

// ---------------- fused persistent kernel ----------------------------------
__global__ void __launch_bounds__(256, 1) k_fused(
    const float* __restrict__ x,
    const float* __restrict__ h_prev, const float* __restrict__ c_prev,
    const float* __restrict__ Wout,  const float* __restrict__ bout,
    float* __restrict__ yhat, float* __restrict__ hseq, float* __restrict__ cseq)
{
    extern __shared__ float sm[];
    const int tid = threadIdx.x;
    __shared__ unsigned s_widx;

    if (blockIdx.x < NR) {
        // ================= RECURRENT ROLE =================
        float* hs = sm;                        // 256*72: h as tf32 [d][b]
        float* pp = sm + H_SZ * HS_STRIDE;     // 2 * 64*20: k-half partials

        const int cta  = blockIdx.x;
        const int lane = tid & 31;
        const int w    = tid >> 5;
        const int mt   = w & 3;                // m-tile: rows [mt*16, +16)
        const int kh   = w >> 2;               // k-half: d in [kh*128, +128)
        const int b0   = mt * 16;
        const int dbase = kh * 128;
        const int lq = lane >> 2;              // 0..7
        const int lr = lane & 3;               // 0..3

        // Wp B-fragments, 2 n-tiles of 8 cols, register-resident all steps
        unsigned bf00[16], bf01[16], bf10[16], bf11[16];
#pragma unroll
        for (int ks = 0; ks < 16; ks++) {
            int d = dbase + ks * 8;
            int c0 = cta * 16 + lq;
            bf00[ks] = f2tf32(g_Wp[(d + lr)     * C4 + c0]);
            bf01[ks] = f2tf32(g_Wp[(d + 4 + lr) * C4 + c0]);
            bf10[ks] = f2tf32(g_Wp[(d + lr)     * C4 + c0 + 8]);
            bf11[ks] = f2tf32(g_Wp[(d + 4 + lr) * C4 + c0 + 8]);
        }

        // init transposed h state: this CTA's 4 neuron rows
        {
            int jl = tid >> 6, bb = tid & 63;
            g_hT[0][(cta * 4 + jl) * B_SZ + bb] =
                h_prev[bb * H_SZ + cta * 4 + jl];
        }

        // every thread is a gate thread: (b, local neuron nl)
        const int gb = tid & 63;
        const int nl = tid >> 6;
        const int gj = cta * 4 + nl;
        float creg = c_prev[gb * H_SZ + gj];

        unsigned base;
        {
            __shared__ unsigned sb;
            if (tid == 0) sb = ld_acq(&g_epoch);
            __syncthreads();
            base = sb;
        }
        unsigned nbar = 0;

        GRIDBAR();   // hT init visible everywhere

        for (int t = 0; t < T_LEN; t++) {
            const int par = t & 1;

            // stage h [d][b] into smem as tf32 (bypass L1: remote writes)
            const float4* src = (const float4*)&g_hT[par][0];
#pragma unroll
            for (int i = 0; i < 16; i++) {
                int f4  = tid + i * 256;
                float4 v = __ldcg(&src[f4]);
                int row = f4 >> 4;
                int col = (f4 & 15) * 4;
                float* dst = &hs[row * HS_STRIDE + col];
                dst[0] = __uint_as_float(f2tf32(v.x));
                dst[1] = __uint_as_float(f2tf32(v.y));
                dst[2] = __uint_as_float(f2tf32(v.z));
                dst[3] = __uint_as_float(f2tf32(v.w));
            }
            // wait for this step's Z m-tile (covers 2 steps); acquire + fence
            if ((t & 1) == 0 && tid == 0) {
                while ((int)ld_acq(&g_zdone[t >> 1]) < Z_NTILES) { }
                __threadfence();
            }
            __syncthreads();

            // Z for this gate thread (produced by workers; L2-coherent)
            const float4 z = __ldcg((const float4*)
                &g_Z[((size_t)t * B_SZ + gb) * C4 + cta * 16 + nl * 4]);

            // mma: P[64 x 16] = h[64 x 256(kh half)] * Wp
            float acc0[4] = {0.f, 0.f, 0.f, 0.f};
            float acc1[4] = {0.f, 0.f, 0.f, 0.f};
#pragma unroll
            for (int ks = 0; ks < 16; ks++) {
                int d = dbase + ks * 8;
                const float* p = &hs[(d + lr) * HS_STRIDE + b0 + lq];
                unsigned a[4];
                a[0] = __float_as_uint(p[0]);
                a[1] = __float_as_uint(p[8]);
                a[2] = __float_as_uint(p[4 * HS_STRIDE]);
                a[3] = __float_as_uint(p[4 * HS_STRIDE + 8]);
                mma_tf32(acc0, a, bf00[ks], bf01[ks]);
                mma_tf32(acc1, a, bf10[ks], bf11[ks]);
            }

            // partials: row (b0+lq[,+8]), cols nt*8 + 2*lr
            {
                float* ppk = pp + kh * (B_SZ * 20);
                *(float2*)&ppk[(b0 + lq)     * 20 + lr * 2]     = make_float2(acc0[0], acc0[1]);
                *(float2*)&ppk[(b0 + lq + 8) * 20 + lr * 2]     = make_float2(acc0[2], acc0[3]);
                *(float2*)&ppk[(b0 + lq)     * 20 + 8 + lr * 2] = make_float2(acc1[0], acc1[1]);
                *(float2*)&ppk[(b0 + lq + 8) * 20 + 8 + lr * 2] = make_float2(acc1[2], acc1[3]);
            }
            __syncthreads();

            {
                const float4 q0 = *(const float4*)&pp[gb * 20 + nl * 4];
                const float4 q1 = *(const float4*)&pp[B_SZ * 20 + gb * 20 + nl * 4];
                float p0 = q0.x + q1.x + z.x;
                float p1 = q0.y + q1.y + z.y;
                float p2 = q0.z + q1.z + z.z;
                float p3 = q0.w + q1.w + z.w;

                float f  = 1.f / (1.f + expf(-p0));
                float ig = 1.f / (1.f + expf(-p1));
                float o  = 1.f / (1.f + expf(-p2));
                float g  = tanhf(p3);
                creg = f * creg + ig * g;
                float hn = o * tanhf(creg);

                g_hT[par ^ 1][gj * B_SZ + gb] = hn;
                size_t off = (size_t)(gb * T_LEN + t) * H_SZ + gj;
                hseq[off] = hn;
                cseq[off] = creg;
                __threadfence();
            }
            GRIDBAR();
        }
        // falls through to Y queue below
    } else {
        // ================= WORKER ROLE: produce Z in t-order =================
        float* As = sm;                        // [16][132]
        float* Bs = sm + 16 * 132;             // [16][68]
        const int wkid = blockIdx.x - NR;
        const int tx = tid & 15, ty = tid >> 4;

        for (unsigned tile = wkid; tile < Z_MTILES * Z_NTILES; tile += NW) {
            const int mtile = tile >> 4;
            const int col0  = (tile & 15) * 64;
            const int row0  = mtile * 128;     // row r = t*64 + b

            float acc[8][4];
#pragma unroll
            for (int m = 0; m < 8; m++)
#pragma unroll
                for (int n = 0; n < 4; n++) acc[m][n] = 0.f;

            for (int k0 = 0; k0 < D_SZ; k0 += 16) {
#pragma unroll
                for (int i = tid; i < 512; i += 256) {
                    int r  = i >> 2, c4 = i & 3;
                    int gr = row0 + r;
                    int tt = gr >> 6, bb = gr & 63;
                    float4 v = *(const float4*)
                        &x[((size_t)bb * T_LEN + tt) * D_SZ + k0 + c4 * 4];
                    As[(c4 * 4 + 0) * 132 + r] = v.x;
                    As[(c4 * 4 + 1) * 132 + r] = v.y;
                    As[(c4 * 4 + 2) * 132 + r] = v.z;
                    As[(c4 * 4 + 3) * 132 + r] = v.w;
                }
                {
                    int r = tid >> 4, c4 = tid & 15;
                    *(float4*)&Bs[r * 68 + c4 * 4] =
                        *(const float4*)&g_M2[(size_t)(k0 + r) * C4 + col0 + c4 * 4];
                }
                __syncthreads();
#pragma unroll
                for (int k = 0; k < 16; k++) {
                    float a[8], bb4[4];
#pragma unroll
                    for (int m = 0; m < 8; m++) a[m] = As[k * 132 + ty * 8 + m];
#pragma unroll
                    for (int n = 0; n < 4; n++) bb4[n] = Bs[k * 68 + tx * 4 + n];
#pragma unroll
                    for (int m = 0; m < 8; m++)
#pragma unroll
                        for (int n = 0; n < 4; n++)
                            acc[m][n] = fmaf(a[m], bb4[n], acc[m][n]);
                }
                __syncthreads();
            }
            float4 bv = *(const float4*)&g_bias2[col0 + tx * 4];
#pragma unroll
            for (int m = 0; m < 8; m++) {
                float4 o;
                o.x = acc[m][0] + bv.x; o.y = acc[m][1] + bv.y;
                o.z = acc[m][2] + bv.z; o.w = acc[m][3] + bv.w;
                *(float4*)&g_Z[(size_t)(row0 + ty * 8 + m) * C4 + col0 + tx * 4] = o;
            }
            __threadfence();
            __syncthreads();
            if (tid == 0) atomicAdd(&g_zdone[mtile], 1);
        }
    }

    // ================= SHARED Y QUEUE: y = hseq * Wout + bout =================
    {
        float* As = sm;
        float* Bs = sm + 16 * 132;
        const int tx = tid & 15, ty = tid >> 4;

        for (;;) {
            __syncthreads();
            if (tid == 0) s_widx = atomicAdd(&g_ywork, 1);
            __syncthreads();
            unsigned idx = s_widx;
            if (idx >= Y_TILES) break;

            const int tchunk = idx >> 8;           // 0..7
            const int rest   = idx & 255;
            const int bb     = rest >> 2;          // batch
            const int col0   = (rest & 3) * 64;
            const int row0   = bb * T_LEN + tchunk * 128;   // rows contiguous in t

            if (tid == 0) {
                unsigned need = (unsigned)(tchunk * 128 + 128);
                while (ld_acq(&g_step) < need) { }
                __threadfence();
            }
            __syncthreads();

            float acc[8][4];
#pragma unroll
            for (int m = 0; m < 8; m++)
#pragma unroll
                for (int n = 0; n < 4; n++) acc[m][n] = 0.f;

            for (int k0 = 0; k0 < H_SZ; k0 += 16) {
#pragma unroll
                for (int i = tid; i < 512; i += 256) {
                    int r  = i >> 2, c4 = i & 3;
                    float4 v = __ldcg((const float4*)
                        &hseq[(size_t)(row0 + r) * H_SZ + k0 + c4 * 4]);
                    As[(c4 * 4 + 0) * 132 + r] = v.x;
                    As[(c4 * 4 + 1) * 132 + r] = v.y;
                    As[(c4 * 4 + 2) * 132 + r] = v.z;
                    As[(c4 * 4 + 3) * 132 + r] = v.w;
                }
                {
                    int r = tid >> 4, c4 = tid & 15;
                    *(float4*)&Bs[r * 68 + c4 * 4] =
                        *(const float4*)&Wout[(size_t)(k0 + r) * D_SZ + col0 + c4 * 4];
                }
                __syncthreads();
#pragma unroll
                for (int k = 0; k < 16; k++) {
                    float a[8], bb4[4];
#pragma unroll
                    for (int m = 0; m < 8; m++) a[m] = As[k * 132 + ty * 8 + m];
#pragma unroll
                    for (int n = 0; n < 4; n++) bb4[n] = Bs[k * 68 + tx * 4 + n];
#pragma unroll
                    for (int m = 0; m < 8; m++)
#pragma unroll
                        for (int n = 0; n < 4; n++)
                            acc[m][n] = fmaf(a[m], bb4[n], acc[m][n]);
                }
                __syncthreads();
            }
            float4 bv = *(const float4*)&bout[col0 + tx * 4];
#pragma unroll
            for (int m = 0; m < 8; m++) {
                float4 o;
                o.x = acc[m][0] + bv.x; o.y = acc[m][1] + bv.y;
                o.z = acc[m][2] + bv.z; o.w = acc[m][3] + bv.w;
                *(float4*)&yhat[(size_t)(row0 + ty * 8 + m) * D_SZ + col0 + tx * 4] = o;
            }
        }
    }
}

// ---------------- launch --------------------------------------------------
extern "C" void kernel_launch(void* const* d_in, const int* in_sizes, int n_in,
                              void* d_out, int out_size) {
    const float* x    = (const float*)d_in[0];
    const float* h0   = (const float*)d_in[1];
    const float* c0   = (const float*)d_in[2];
    const float* Win  = (const float*)d_in[3];
    const float* Wx   = (const float*)d_in[4];
    const float* Wh   = (const float*)d_in[5];
    const float* We   = (const float*)d_in[6];
    const float* bb   = (const float*)d_in[7];
    const float* Wout = (const float*)d_in[8];
    const float* bout = (const float*)d_in[9];

    float* out  = (float*)d_out;
    float* yhat = out;                                   // [B,T,D]
    float* hseq = out + (size_t)B_SZ * T_LEN * D_SZ;     // [B,T,H]
    float* cseq = hseq + (size_t)B_SZ * T_LEN * H_SZ;    // [B,T,H]

    k_prepM<<<dim3(4, 256), 256>>>(Win, Wx, We, bb);
    k_prepW<<<dim3(4, 256), 256>>>(Wh, We);
    k_reset<<<1, 512>>>();

    const int smemB = (H_SZ * HS_STRIDE + 2 * B_SZ * 20) * 4;   // 83968 B
    cudaFuncSetAttribute(k_fused, cudaFuncAttributeMaxDynamicSharedMemorySize,
                         smemB);
    k_fused<<<NTOT, 256, smemB>>>(x, h0, c0, Wout, bout, yhat, hseq, cseq);
}

// round 7
// speedup vs baseline: 1.0189x; 1.0189x over previous
#include <cuda_runtime.h>
#include <math.h>

#define T_LEN 1024
#define B_SZ  64
#define H_SZ  256
#define D_SZ  256
#define C4    1024          // 4*H, col = j*4 + k (gates of a neuron contiguous)
#define NR    64            // recurrent CTAs (4 neurons / 16 cols each)
#define NW    84            // worker CTAs
#define NTOT  (NR + NW)     // 148 total, all co-resident
#define HS_STRIDE 72        // padded word stride for hs[d][b]
#define AS_STR 132          // padded stride for GEMM A-tiles [k][m]

#define Z_MTILES 512        // 65536 rows / 128
#define Z_NTILES 8          // 1024 / 128
#define Z_TILES  (Z_MTILES * Z_NTILES)
#define Y_TILES  1024       // 512 mtiles * 2 ntiles (256 cols / 128)

// ---------------- scratch (static device allocations only) ----------------
__device__ float g_M2[D_SZ * C4];            // folded x-projection  [d][col]
__device__ float g_bias2[C4];
__device__ float g_Wp[H_SZ * C4];            // folded recurrent (Wh - We)
__device__ float g_Z[(size_t)T_LEN * B_SZ * C4];   // t-major: [t][b][1024]
__device__ float g_hT[2][H_SZ * B_SZ];       // h state [j][b], double buffered
__device__ unsigned g_count;                 // grid barrier (recur CTAs)
__device__ unsigned g_epoch;                 // monotonic across replays
__device__ unsigned g_step;                  // steps completed THIS run
__device__ int      g_zdone[Z_MTILES];       // per-mtile completed n-tiles
__device__ unsigned g_ywork;                 // Y tile work queue

// ---------------- acquire/release primitives -------------------------------
__device__ __forceinline__ unsigned ld_acq(const void* p) {
    unsigned v;
    asm volatile("ld.acquire.gpu.b32 %0, [%1];" : "=r"(v) : "l"(p) : "memory");
    return v;
}
__device__ __forceinline__ void st_rel(void* p, unsigned v) {
    asm volatile("st.release.gpu.b32 [%0], %1;" :: "l"(p), "r"(v) : "memory");
}

// ---------------- tf32 mma helpers ----------------------------------------
__device__ __forceinline__ unsigned f2tf32(float x) {
    unsigned r;
    asm("cvt.rna.tf32.f32 %0, %1;" : "=r"(r) : "f"(x));
    return r;
}
__device__ __forceinline__ void mma_tf32(float* c, const unsigned* a,
                                         unsigned b0, unsigned b1) {
    asm volatile(
        "mma.sync.aligned.m16n8k8.row.col.f32.tf32.tf32.f32 "
        "{%0,%1,%2,%3}, {%4,%5,%6,%7}, {%8,%9}, {%0,%1,%2,%3};"
        : "+f"(c[0]), "+f"(c[1]), "+f"(c[2]), "+f"(c[3])
        : "r"(a[0]), "r"(a[1]), "r"(a[2]), "r"(a[3]), "r"(b0), "r"(b1));
}

// ---------------- prep kernels --------------------------------------------
__global__ void k_prepM(const float* __restrict__ Win, const float* __restrict__ Wx,
                        const float* __restrict__ We, const float* __restrict__ b) {
    int k = blockIdx.x, d = blockIdx.y, j = threadIdx.x;
    float acc = Wx[(k * D_SZ + d) * H_SZ + j];
    const float* wrow = &Win[d * H_SZ];
#pragma unroll 8
    for (int e = 0; e < H_SZ; e++)
        acc = fmaf(__ldg(&wrow[e]), __ldg(&We[(k * H_SZ + e) * H_SZ + j]), acc);
    g_M2[d * C4 + j * 4 + k] = acc;
    if (d == 0) g_bias2[j * 4 + k] = b[k * H_SZ + j];
}

__global__ void k_prepW(const float* __restrict__ Wh, const float* __restrict__ We) {
    int k = blockIdx.x, h = blockIdx.y, j = threadIdx.x;
    int src = (k * H_SZ + h) * H_SZ + j;
    g_Wp[h * C4 + j * 4 + k] = Wh[src] - We[src];
}

__global__ void k_reset() {
    int i = threadIdx.x;
    if (i < Z_MTILES) g_zdone[i] = 0;
    if (i == 0) { g_step = 0; g_ywork = 0; g_count = 0; }
    __threadfence();
}

// ---------------- grid barrier for the NR recurrent CTAs -------------------
#define GRIDBAR()                                                          \
    do {                                                                   \
        __syncthreads();                                                   \
        nbar++;                                                            \
        if (tid == 0) {                                                    \
            __threadfence();                                               \
            unsigned prev = atomicAdd(&g_count, 1);                        \
            if (prev == NR - 1) {                                          \
                atomicExch(&g_count, 0);                                   \
                __threadfence();                                           \
                st_rel(&g_step, nbar - 1);                                 \
                st_rel(&g_epoch, base + nbar);                             \
            } else {                                                       \
                while (ld_acq(&g_epoch) - base < nbar) { }                 \
            }                                                              \
            __threadfence();                                               \
        }                                                                  \
        __syncthreads();                                                   \
    } while (0)

// ---------------- fused persistent kernel ----------------------------------
__global__ void __launch_bounds__(256, 1) k_fused(
    const float* __restrict__ x,
    const float* __restrict__ h_prev, const float* __restrict__ c_prev,
    const float* __restrict__ Wout,  const float* __restrict__ bout,
    float* __restrict__ yhat, float* __restrict__ hseq, float* __restrict__ cseq)
{
    extern __shared__ float sm[];
    const int tid = threadIdx.x;
    __shared__ unsigned s_widx;

    // GEMM thread mapping (worker + Y phases)
    const int tx = tid & 15;          // col group: cols tx*4 and 64+tx*4
    const int ty = tid >> 4;          // row group: rows ty*8..+7
    const int rA = tid >> 2;          // A-load row (0..63), also +64
    const int cA = (tid & 3) * 4;     // A-load k offset
    const int rB = tid >> 4;          // B-load row (0..15)
    const int cB = (tid & 15) * 4;    // B-load col offset, also +64

    if (blockIdx.x < NR) {
        // ================= RECURRENT ROLE =================
        float* hs = sm;                        // 256*72: h as tf32 [d][b]
        float* pp = sm + H_SZ * HS_STRIDE;     // 2 * 64*20: k-half partials

        const int cta  = blockIdx.x;
        const int lane = tid & 31;
        const int w    = tid >> 5;
        const int mt   = w & 3;                // m-tile: rows [mt*16, +16)
        const int kh   = w >> 2;               // k-half: d in [kh*128, +128)
        const int b0   = mt * 16;
        const int dbase = kh * 128;
        const int lq = lane >> 2;              // 0..7
        const int lr = lane & 3;               // 0..3

        // Wp B-fragments, 2 n-tiles of 8 cols, register-resident all steps
        unsigned bf00[16], bf01[16], bf10[16], bf11[16];
#pragma unroll
        for (int ks = 0; ks < 16; ks++) {
            int d = dbase + ks * 8;
            int c0 = cta * 16 + lq;
            bf00[ks] = f2tf32(g_Wp[(d + lr)     * C4 + c0]);
            bf01[ks] = f2tf32(g_Wp[(d + 4 + lr) * C4 + c0]);
            bf10[ks] = f2tf32(g_Wp[(d + lr)     * C4 + c0 + 8]);
            bf11[ks] = f2tf32(g_Wp[(d + 4 + lr) * C4 + c0 + 8]);
        }

        // init transposed h state: this CTA's 4 neuron rows
        {
            int jl = tid >> 6, bb = tid & 63;
            g_hT[0][(cta * 4 + jl) * B_SZ + bb] =
                h_prev[bb * H_SZ + cta * 4 + jl];
        }

        // every thread is a gate thread: (b, local neuron nl)
        const int gb = tid & 63;
        const int nl = tid >> 6;
        const int gj = cta * 4 + nl;
        float creg = c_prev[gb * H_SZ + gj];

        unsigned base;
        {
            __shared__ unsigned sb;
            if (tid == 0) sb = ld_acq(&g_epoch);
            __syncthreads();
            base = sb;
        }
        unsigned nbar = 0;

        GRIDBAR();   // hT init visible everywhere

        for (int t = 0; t < T_LEN; t++) {
            const int par = t & 1;

            // stage h [d][b] into smem as tf32 (bypass L1: remote writes)
            const float4* src = (const float4*)&g_hT[par][0];
#pragma unroll
            for (int i = 0; i < 16; i++) {
                int f4  = tid + i * 256;
                float4 v = __ldcg(&src[f4]);
                int row = f4 >> 4;
                int col = (f4 & 15) * 4;
                float* dst = &hs[row * HS_STRIDE + col];
                dst[0] = __uint_as_float(f2tf32(v.x));
                dst[1] = __uint_as_float(f2tf32(v.y));
                dst[2] = __uint_as_float(f2tf32(v.z));
                dst[3] = __uint_as_float(f2tf32(v.w));
            }
            // wait for this step's Z m-tile (covers 2 steps); acquire + fence
            if ((t & 1) == 0 && tid == 0) {
                while ((int)ld_acq(&g_zdone[t >> 1]) < Z_NTILES) { }
                __threadfence();
            }
            __syncthreads();

            // Z for this gate thread (produced by workers; L2-coherent)
            const float4 z = __ldcg((const float4*)
                &g_Z[((size_t)t * B_SZ + gb) * C4 + cta * 16 + nl * 4]);

            // mma: P[64 x 16] = h[64 x 256(kh half)] * Wp
            float acc0[4] = {0.f, 0.f, 0.f, 0.f};
            float acc1[4] = {0.f, 0.f, 0.f, 0.f};
#pragma unroll
            for (int ks = 0; ks < 16; ks++) {
                int d = dbase + ks * 8;
                const float* p = &hs[(d + lr) * HS_STRIDE + b0 + lq];
                unsigned a[4];
                a[0] = __float_as_uint(p[0]);
                a[1] = __float_as_uint(p[8]);
                a[2] = __float_as_uint(p[4 * HS_STRIDE]);
                a[3] = __float_as_uint(p[4 * HS_STRIDE + 8]);
                mma_tf32(acc0, a, bf00[ks], bf01[ks]);
                mma_tf32(acc1, a, bf10[ks], bf11[ks]);
            }

            // partials: row (b0+lq[,+8]), cols nt*8 + 2*lr
            {
                float* ppk = pp + kh * (B_SZ * 20);
                *(float2*)&ppk[(b0 + lq)     * 20 + lr * 2]     = make_float2(acc0[0], acc0[1]);
                *(float2*)&ppk[(b0 + lq + 8) * 20 + lr * 2]     = make_float2(acc0[2], acc0[3]);
                *(float2*)&ppk[(b0 + lq)     * 20 + 8 + lr * 2] = make_float2(acc1[0], acc1[1]);
                *(float2*)&ppk[(b0 + lq + 8) * 20 + 8 + lr * 2] = make_float2(acc1[2], acc1[3]);
            }
            __syncthreads();

            {
                const float4 q0 = *(const float4*)&pp[gb * 20 + nl * 4];
                const float4 q1 = *(const float4*)&pp[B_SZ * 20 + gb * 20 + nl * 4];
                float p0 = q0.x + q1.x + z.x;
                float p1 = q0.y + q1.y + z.y;
                float p2 = q0.z + q1.z + z.z;
                float p3 = q0.w + q1.w + z.w;

                float f  = 1.f / (1.f + expf(-p0));
                float ig = 1.f / (1.f + expf(-p1));
                float o  = 1.f / (1.f + expf(-p2));
                float g  = tanhf(p3);
                creg = f * creg + ig * g;
                float hn = o * tanhf(creg);

                g_hT[par ^ 1][gj * B_SZ + gb] = hn;
                size_t off = (size_t)(gb * T_LEN + t) * H_SZ + gj;
                hseq[off] = hn;
                cseq[off] = creg;
                __threadfence();
            }
            GRIDBAR();
        }
        // falls through to Y queue below
    } else {
        // ===== WORKER ROLE: produce Z in t-order, 128x128 pipelined tiles =====
        float* As = sm;                        // [16][AS_STR] transposed A
        float* Bs = sm + 16 * AS_STR;          // [16][128]
        const int wkid = blockIdx.x - NR;

        for (unsigned tile = wkid; tile < Z_TILES; tile += NW) {
            const int mtile = tile >> 3;
            const int col0  = (tile & 7) * 128;
            const int row0  = mtile * 128;     // row r = t*64 + b

            const int gr0 = row0 + rA;
            const int gr1 = gr0 + 64;
            const float* pa0 = &x[((size_t)(gr0 & 63) * T_LEN + (gr0 >> 6)) * D_SZ + cA];
            const float* pa1 = &x[((size_t)(gr1 & 63) * T_LEN + (gr1 >> 6)) * D_SZ + cA];
            const float* pb  = &g_M2[(size_t)rB * C4 + col0 + cB];

            // prologue: k-block 0 into registers
            float4 ra0 = *(const float4*)pa0;
            float4 ra1 = *(const float4*)pa1;
            float4 rb0 = *(const float4*)pb;
            float4 rb1 = *(const float4*)(pb + 64);

            float acc[8][8];
#pragma unroll
            for (int m = 0; m < 8; m++)
#pragma unroll
                for (int n = 0; n < 8; n++) acc[m][n] = 0.f;

            for (int kb = 0; kb < 16; kb++) {
                // stage registers -> smem (A transposed to [k][m])
                As[(cA + 0) * AS_STR + rA]      = ra0.x;
                As[(cA + 1) * AS_STR + rA]      = ra0.y;
                As[(cA + 2) * AS_STR + rA]      = ra0.z;
                As[(cA + 3) * AS_STR + rA]      = ra0.w;
                As[(cA + 0) * AS_STR + rA + 64] = ra1.x;
                As[(cA + 1) * AS_STR + rA + 64] = ra1.y;
                As[(cA + 2) * AS_STR + rA + 64] = ra1.z;
                As[(cA + 3) * AS_STR + rA + 64] = ra1.w;
                *(float4*)&Bs[rB * 128 + cB]      = rb0;
                *(float4*)&Bs[rB * 128 + cB + 64] = rb1;
                __syncthreads();

                // prefetch next k-block (hidden under compute)
                if (kb < 15) {
                    int k0 = (kb + 1) * 16;
                    ra0 = *(const float4*)(pa0 + k0);
                    ra1 = *(const float4*)(pa1 + k0);
                    rb0 = *(const float4*)(pb + (size_t)k0 * C4);
                    rb1 = *(const float4*)(pb + (size_t)k0 * C4 + 64);
                }

#pragma unroll
                for (int k = 0; k < 16; k++) {
                    float a[8], bb8[8];
                    *(float4*)&a[0]   = *(const float4*)&As[k * AS_STR + ty * 8];
                    *(float4*)&a[4]   = *(const float4*)&As[k * AS_STR + ty * 8 + 4];
                    *(float4*)&bb8[0] = *(const float4*)&Bs[k * 128 + tx * 4];
                    *(float4*)&bb8[4] = *(const float4*)&Bs[k * 128 + 64 + tx * 4];
#pragma unroll
                    for (int m = 0; m < 8; m++)
#pragma unroll
                        for (int n = 0; n < 8; n++)
                            acc[m][n] = fmaf(a[m], bb8[n], acc[m][n]);
                }
                __syncthreads();
            }

            const float4 bv0 = *(const float4*)&g_bias2[col0 + tx * 4];
            const float4 bv1 = *(const float4*)&g_bias2[col0 + 64 + tx * 4];
#pragma unroll
            for (int m = 0; m < 8; m++) {
                float* zr = &g_Z[(size_t)(row0 + ty * 8 + m) * C4 + col0];
                float4 o0, o1;
                o0.x = acc[m][0] + bv0.x; o0.y = acc[m][1] + bv0.y;
                o0.z = acc[m][2] + bv0.z; o0.w = acc[m][3] + bv0.w;
                o1.x = acc[m][4] + bv1.x; o1.y = acc[m][5] + bv1.y;
                o1.z = acc[m][6] + bv1.z; o1.w = acc[m][7] + bv1.w;
                *(float4*)&zr[tx * 4]      = o0;
                *(float4*)&zr[64 + tx * 4] = o1;
            }
            __threadfence();
            __syncthreads();
            if (tid == 0) atomicAdd(&g_zdone[mtile], 1);
        }
    }

    // ====== SHARED Y QUEUE: y = hseq * Wout + bout, 128x128 pipelined ======
    {
        float* As = sm;
        float* Bs = sm + 16 * AS_STR;

        for (;;) {
            __syncthreads();
            if (tid == 0) s_widx = atomicAdd(&g_ywork, 1);
            __syncthreads();
            unsigned idx = s_widx;
            if (idx >= Y_TILES) break;

            const int tchunk = idx >> 7;            // 0..7
            const int rest   = idx & 127;
            const int bb     = rest >> 1;           // batch
            const int col0   = (idx & 1) * 128;
            const int row0   = bb * T_LEN + tchunk * 128;   // rows contiguous in t

            if (tid == 0) {
                unsigned need = (unsigned)(tchunk * 128 + 128);
                while (ld_acq(&g_step) < need) { }
                __threadfence();
            }
            __syncthreads();

            const float* pa0 = &hseq[(size_t)(row0 + rA) * H_SZ + cA];
            const float* pa1 = pa0 + (size_t)64 * H_SZ;
            const float* pb  = &Wout[(size_t)rB * D_SZ + col0 + cB];

            float4 ra0 = __ldcg((const float4*)pa0);
            float4 ra1 = __ldcg((const float4*)pa1);
            float4 rb0 = *(const float4*)pb;
            float4 rb1 = *(const float4*)(pb + 64);

            float acc[8][8];
#pragma unroll
            for (int m = 0; m < 8; m++)
#pragma unroll
                for (int n = 0; n < 8; n++) acc[m][n] = 0.f;

            for (int kb = 0; kb < 16; kb++) {
                As[(cA + 0) * AS_STR + rA]      = ra0.x;
                As[(cA + 1) * AS_STR + rA]      = ra0.y;
                As[(cA + 2) * AS_STR + rA]      = ra0.z;
                As[(cA + 3) * AS_STR + rA]      = ra0.w;
                As[(cA + 0) * AS_STR + rA + 64] = ra1.x;
                As[(cA + 1) * AS_STR + rA + 64] = ra1.y;
                As[(cA + 2) * AS_STR + rA + 64] = ra1.z;
                As[(cA + 3) * AS_STR + rA + 64] = ra1.w;
                *(float4*)&Bs[rB * 128 + cB]      = rb0;
                *(float4*)&Bs[rB * 128 + cB + 64] = rb1;
                __syncthreads();

                if (kb < 15) {
                    int k0 = (kb + 1) * 16;
                    ra0 = __ldcg((const float4*)(pa0 + k0));
                    ra1 = __ldcg((const float4*)(pa1 + k0));
                    rb0 = *(const float4*)(pb + (size_t)k0 * D_SZ);
                    rb1 = *(const float4*)(pb + (size_t)k0 * D_SZ + 64);
                }

#pragma unroll
                for (int k = 0; k < 16; k++) {
                    float a[8], bb8[8];
                    *(float4*)&a[0]   = *(const float4*)&As[k * AS_STR + ty * 8];
                    *(float4*)&a[4]   = *(const float4*)&As[k * AS_STR + ty * 8 + 4];
                    *(float4*)&bb8[0] = *(const float4*)&Bs[k * 128 + tx * 4];
                    *(float4*)&bb8[4] = *(const float4*)&Bs[k * 128 + 64 + tx * 4];
#pragma unroll
                    for (int m = 0; m < 8; m++)
#pragma unroll
                        for (int n = 0; n < 8; n++)
                            acc[m][n] = fmaf(a[m], bb8[n], acc[m][n]);
                }
                __syncthreads();
            }

            const float4 bv0 = *(const float4*)&bout[col0 + tx * 4];
            const float4 bv1 = *(const float4*)&bout[col0 + 64 + tx * 4];
#pragma unroll
            for (int m = 0; m < 8; m++) {
                float* yr = &yhat[(size_t)(row0 + ty * 8 + m) * D_SZ + col0];
                float4 o0, o1;
                o0.x = acc[m][0] + bv0.x; o0.y = acc[m][1] + bv0.y;
                o0.z = acc[m][2] + bv0.z; o0.w = acc[m][3] + bv0.w;
                o1.x = acc[m][4] + bv1.x; o1.y = acc[m][5] + bv1.y;
                o1.z = acc[m][6] + bv1.z; o1.w = acc[m][7] + bv1.w;
                *(float4*)&yr[tx * 4]      = o0;
                *(float4*)&yr[64 + tx * 4] = o1;
            }
        }
    }
}

// ---------------- launch --------------------------------------------------
extern "C" void kernel_launch(void* const* d_in, const int* in_sizes, int n_in,
                              void* d_out, int out_size) {
    const float* x    = (const float*)d_in[0];
    const float* h0   = (const float*)d_in[1];
    const float* c0   = (const float*)d_in[2];
    const float* Win  = (const float*)d_in[3];
    const float* Wx   = (const float*)d_in[4];
    const float* Wh   = (const float*)d_in[5];
    const float* We   = (const float*)d_in[6];
    const float* bb   = (const float*)d_in[7];
    const float* Wout = (const float*)d_in[8];
    const float* bout = (const float*)d_in[9];

    float* out  = (float*)d_out;
    float* yhat = out;                                   // [B,T,D]
    float* hseq = out + (size_t)B_SZ * T_LEN * D_SZ;     // [B,T,H]
    float* cseq = hseq + (size_t)B_SZ * T_LEN * H_SZ;    // [B,T,H]

    k_prepM<<<dim3(4, 256), 256>>>(Win, Wx, We, bb);
    k_prepW<<<dim3(4, 256), 256>>>(Wh, We);
    k_reset<<<1, 512>>>();

    const int smemB = (H_SZ * HS_STRIDE + 2 * B_SZ * 20) * 4;   // 83968 B
    cudaFuncSetAttribute(k_fused, cudaFuncAttributeMaxDynamicSharedMemorySize,
                         smemB);
    k_fused<<<NTOT, 256, smemB>>>(x, h0, c0, Wout, bout, yhat, hseq, cseq);
}